// round 1
// baseline (speedup 1.0000x reference)
#include <cuda_runtime.h>
#include <math.h>
#include <stdint.h>

// ---------------------------------------------------------------------------
// Beam search generator: B=16, BEAM=4, MAX_LEN=16, VOCAB=32000, D=512, S=128
// Inputs (metadata order): src_input [16,128] i32, E_src [32000,512] f32,
//                          E_tgt [32000,512] f32, W [512,32000] f32, b [32000] f32
// Output: fin_seq[:,0] -> [16,16] int32
// ---------------------------------------------------------------------------

#define B_      16
#define BEAM_   4
#define MAXLEN_ 16
#define V_      32000
#define D_      512
#define S_      128
#define NR_     64          // B_*BEAM_ decoder rows
#define NEG_INF_PEN 1e9f

// ------------------------------ device state --------------------------------
static __device__ __align__(16) float g_pooled[B_ * D_];
static __device__ __align__(16) float g_xT[D_ * NR_];          // x transposed [k][row]
static __device__ __align__(16) float g_logits[(size_t)NR_ * V_];
static __device__ float g_rowmax[NR_];
static __device__ float g_rowlogz[NR_];
static __device__ float g_alive_lp[B_ * BEAM_];
static __device__ int   g_alive_seq[B_ * BEAM_ * MAXLEN_];
static __device__ float g_fin_scores[B_ * BEAM_];
static __device__ int   g_fin_seq[B_ * BEAM_ * MAXLEN_];
static __device__ int   g_fin_flags[B_ * BEAM_];
static __device__ int   g_batch_fin[B_];
static __device__ float g_top8_sc[B_ * 8];
static __device__ int   g_top8_id[B_ * 8];

// ------------------------------ helpers -------------------------------------
__device__ __forceinline__ unsigned int ford(float f) {
    unsigned int u = __float_as_uint(f);
    return (u & 0x80000000u) ? ~u : (u | 0x80000000u);
}
__device__ __forceinline__ float finv(unsigned int u) {
    return __uint_as_float((u & 0x80000000u) ? (u ^ 0x80000000u) : ~u);
}
__device__ __forceinline__ unsigned long long umax64(unsigned long long a, unsigned long long b) {
    return a > b ? a : b;
}

// ------------------------------ init -----------------------------------------
__global__ void k_init() {
    int i = threadIdx.x;  // 1024 threads
    // alive_seq and fin_seq each have 16*4*16 = 1024 ints
    g_alive_seq[i] = ((i & (MAXLEN_ - 1)) == 0) ? 1 : 0;   // BOS at position 0
    g_fin_seq[i] = 0;
    if (i < B_ * BEAM_) {
        g_alive_lp[i]   = ((i & (BEAM_ - 1)) == 0) ? 0.0f : -INFINITY;
        g_fin_scores[i] = -NEG_INF_PEN;
        g_fin_flags[i]  = 0;
    }
    if (i < B_) g_batch_fin[i] = 0;
}

// ------------------------------ encoder pooling ------------------------------
__global__ void __launch_bounds__(256) k_pooled(const int* __restrict__ src,
                                                const float* __restrict__ Esrc) {
    int b = blockIdx.x;
    int tid = threadIdx.x;
    __shared__ int toks[S_];
    if (tid < S_) toks[tid] = src[b * S_ + tid];
    __syncthreads();
    float cnt = 0.0f;
    for (int s = 0; s < S_; s++) cnt += (toks[s] != 0) ? 1.0f : 0.0f;
    float denom = fmaxf(cnt, 1.0f);
    for (int d = tid; d < D_; d += blockDim.x) {
        float acc = 0.0f;
        for (int s = 0; s < S_; s++) {
            int tk = toks[s];
            if (tk != 0) acc += Esrc[(size_t)tk * D_ + d];
        }
        g_pooled[b * D_ + d] = __fdiv_rn(acc, denom);
    }
}

// ------------------------------ x prep: xT[k][r] = E_tgt[tok_r][k] + pooled[b][k]
__global__ void k_prep(const float* __restrict__ Etgt, int t) {
    int r = blockIdx.x;            // 0..63
    int b = r >> 2;
    int tok = g_alive_seq[r * MAXLEN_ + t];
    const float* e = Etgt + (size_t)tok * D_;
    const float* p = g_pooled + b * D_;
    for (int k = threadIdx.x; k < D_; k += blockDim.x)
        g_xT[k * NR_ + r] = e[k] + p[k];
}

// ------------------------------ SGEMM: logits[64][32000] = x @ W + bias -------
// Block: 256 threads, tile 64(M) x 128(N), K chunk 16.
// Thread (tm, tn): rows 4*tm..+3, cols {4*tn..+3} U {64+4*tn..+3}.
__global__ void __launch_bounds__(256) k_gemm(const float* __restrict__ W,
                                              const float* __restrict__ bias) {
    const int nb  = blockIdx.x * 128;
    const int tid = threadIdx.x;
    const int tm  = tid >> 4;   // 0..15
    const int tn  = tid & 15;   // 0..15

    __shared__ float xs[16][64];
    __shared__ float ws[16][128];

    float acc[4][8];
#pragma unroll
    for (int i = 0; i < 4; i++)
#pragma unroll
        for (int j = 0; j < 8; j++) acc[i][j] = 0.0f;

    for (int k0 = 0; k0 < D_; k0 += 16) {
        {   // load xT chunk: 16x64 floats = 256 float4, one per thread
            int kk = tid >> 4, m4 = tid & 15;
            float4 v = *reinterpret_cast<const float4*>(g_xT + (k0 + kk) * NR_ + m4 * 4);
            *reinterpret_cast<float4*>(&xs[kk][m4 * 4]) = v;
        }
#pragma unroll
        for (int j = 0; j < 2; j++) {  // load W chunk: 16x128 floats = 512 float4
            int idx = tid + j * 256;
            int kk = idx >> 5, n4 = idx & 31;
            float4 v = *reinterpret_cast<const float4*>(W + (size_t)(k0 + kk) * V_ + nb + n4 * 4);
            *reinterpret_cast<float4*>(&ws[kk][n4 * 4]) = v;
        }
        __syncthreads();
#pragma unroll
        for (int kk = 0; kk < 16; kk++) {
            float4 a4 = *reinterpret_cast<float4*>(&xs[kk][tm * 4]);
            float4 w0 = *reinterpret_cast<float4*>(&ws[kk][tn * 4]);
            float4 w1 = *reinterpret_cast<float4*>(&ws[kk][64 + tn * 4]);
            float av[4] = {a4.x, a4.y, a4.z, a4.w};
            float wv[8] = {w0.x, w0.y, w0.z, w0.w, w1.x, w1.y, w1.z, w1.w};
#pragma unroll
            for (int i = 0; i < 4; i++)
#pragma unroll
                for (int j = 0; j < 8; j++)
                    acc[i][j] = fmaf(av[i], wv[j], acc[i][j]);
        }
        __syncthreads();
    }
#pragma unroll
    for (int i = 0; i < 4; i++) {
        int row = tm * 4 + i;
        int c0 = nb + tn * 4;
        int c1 = nb + 64 + tn * 4;
        float4 o0 = make_float4(acc[i][0] + bias[c0 + 0], acc[i][1] + bias[c0 + 1],
                                acc[i][2] + bias[c0 + 2], acc[i][3] + bias[c0 + 3]);
        float4 o1 = make_float4(acc[i][4] + bias[c1 + 0], acc[i][5] + bias[c1 + 1],
                                acc[i][6] + bias[c1 + 2], acc[i][7] + bias[c1 + 3]);
        *reinterpret_cast<float4*>(g_logits + (size_t)row * V_ + c0) = o0;
        *reinterpret_cast<float4*>(g_logits + (size_t)row * V_ + c1) = o1;
    }
}

// ------------------------------ per-row max + logsumexp ----------------------
__global__ void __launch_bounds__(256) k_rowstats() {
    int r = blockIdx.x, tid = threadIdx.x;
    const float* lrow = g_logits + (size_t)r * V_;
    float m = -INFINITY, s = 0.0f;
    for (int v = tid; v < V_; v += 256) {
        float x = lrow[v];
        if (x > m) { s = s * expf(m - x) + 1.0f; m = x; }
        else       { s += expf(x - m); }
    }
    __shared__ float sm[256], ss[256];
    sm[tid] = m; ss[tid] = s;
    __syncthreads();
    for (int off = 128; off > 0; off >>= 1) {
        if (tid < off) {
            float m1 = sm[tid], s1 = ss[tid];
            float m2 = sm[tid + off], s2 = ss[tid + off];
            if (m2 > m1) { sm[tid] = m2; ss[tid] = s1 * expf(m1 - m2) + s2; }
            else         { ss[tid] = s1 + s2 * expf(m2 - m1); }
        }
        __syncthreads();
    }
    if (tid == 0) { g_rowmax[r] = sm[0]; g_rowlogz[r] = logf(ss[0]); }
}

// ------------------------------ per-batch top-8 over BEAM*VOCAB --------------
// Key = (ordered(score) << 32) | (0xFFFFFFFF - flat_idx): max-key = best score,
// ties broken toward LOWER flat index (matches lax.top_k).
__global__ void __launch_bounds__(256) k_top8(int t) {
    int b = blockIdx.x, tid = threadIdx.x;
    float lpen = (float)(t + 1);
    unsigned long long loc[8];
#pragma unroll
    for (int i = 0; i < 8; i++) loc[i] = 0ull;

    for (int beam = 0; beam < BEAM_; beam++) {
        int r = b * BEAM_ + beam;
        float al = g_alive_lp[r];
        float rm = g_rowmax[r], rz = g_rowlogz[r];
        const float* lrow = g_logits + (size_t)r * V_;
        for (int v = tid; v < V_; v += 256) {
            float lp = (lrow[v] - rm) - rz;                 // log_softmax (same op order)
            float s  = __fdiv_rn(al + lp, lpen);            // flat = log_probs / lpen
            unsigned int idx = (unsigned int)(beam * V_ + v);
            unsigned long long key =
                ((unsigned long long)ford(s) << 32) | (unsigned long long)(0xFFFFFFFFu - idx);
            if (key > loc[7]) {
                loc[7] = key;
#pragma unroll
                for (int i = 7; i > 0; i--) {
                    if (loc[i] > loc[i - 1]) {
                        unsigned long long tmp = loc[i]; loc[i] = loc[i - 1]; loc[i - 1] = tmp;
                    }
                }
            }
        }
    }

    __shared__ unsigned long long pool[256 * 8];
    __shared__ unsigned long long red[256];
#pragma unroll
    for (int i = 0; i < 8; i++) pool[tid * 8 + i] = loc[i];
    __syncthreads();

    for (int sel = 0; sel < 8; sel++) {
        unsigned long long mx = 0ull;
#pragma unroll
        for (int i = 0; i < 8; i++) mx = umax64(mx, pool[tid * 8 + i]);
        red[tid] = mx;
        __syncthreads();
        for (int off = 128; off > 0; off >>= 1) {
            if (tid < off) red[tid] = umax64(red[tid], red[tid + off]);
            __syncthreads();
        }
        unsigned long long w = red[0];
#pragma unroll
        for (int i = 0; i < 8; i++)
            if (pool[tid * 8 + i] == w) pool[tid * 8 + i] = 0ull;  // keys unique
        if (tid == 0) {
            g_top8_sc[b * 8 + sel] = finv((unsigned int)(w >> 32));
            g_top8_id[b * 8 + sel] = (int)(0xFFFFFFFFu - (unsigned int)w);
        }
        __syncthreads();
    }
}

// ------------------------------ beam bookkeeping (1 thread / batch) ----------
__global__ void k_book(int t) {
    int b = threadIdx.x;
    if (b >= B_) return;
    float lpen = (float)(t + 1);

    float sc[8]; int id[8];
    for (int j = 0; j < 8; j++) { sc[j] = g_top8_sc[b * 8 + j]; id[j] = g_top8_id[b * 8 + j]; }

    int tok[8], bix[8], fin[8]; float tlp[8];
    for (int j = 0; j < 8; j++) {
        tok[j] = id[j] % V_;
        bix[j] = (t == 0) ? (j & 3) : (id[j] / V_);
        fin[j] = (tok[j] == 2);
        tlp[j] = sc[j] * lpen;   // topk_lp = topk_scores * lpen (f32, as reference)
    }

    int tseq[8][MAXLEN_];
    for (int j = 0; j < 8; j++) {
        const int* sp = g_alive_seq + (b * BEAM_ + bix[j]) * MAXLEN_;
        for (int l = 0; l < MAXLEN_; l++) tseq[j][l] = sp[l];
        tseq[j][t + 1] = tok[j];
    }

    // --- alive set: top-4 of (score + fin * -1e9), lowest index wins ties
    float curr[8];
    for (int j = 0; j < 8; j++) curr[j] = sc[j] + (fin[j] ? -NEG_INF_PEN : 0.0f);
    int aidx[4];
    {
        bool used[8] = {};
        for (int sel = 0; sel < 4; sel++) {
            int best = -1;
            for (int j = 0; j < 8; j++)
                if (!used[j] && (best < 0 || curr[j] > curr[best])) best = j;
            used[best] = true; aidx[sel] = best;
        }
    }
    float nalp[4]; int naseq[4][MAXLEN_];
    for (int k = 0; k < 4; k++) {
        nalp[k] = tlp[aidx[k]];
        for (int l = 0; l < MAXLEN_; l++) naseq[k][l] = tseq[aidx[k]][l];
    }

    // --- finished set: top-4 of [old fin(4), fs(8)], lowest index wins ties
    float bfp = g_batch_fin[b] ? -NEG_INF_PEN : 0.0f;
    float cs[12]; int cfl[12];
    for (int k = 0; k < 4; k++) {
        cs[k]  = g_fin_scores[b * BEAM_ + k];
        cfl[k] = g_fin_flags[b * BEAM_ + k];
    }
    for (int j = 0; j < 8; j++) {
        cs[4 + j]  = (sc[j] + (fin[j] ? 0.0f : -NEG_INF_PEN)) + bfp;  // same add order as ref
        cfl[4 + j] = fin[j];
    }
    int fidx[4];
    {
        bool used[12] = {};
        for (int sel = 0; sel < 4; sel++) {
            int best = -1;
            for (int j = 0; j < 12; j++)
                if (!used[j] && (best < 0 || cs[j] > cs[best])) best = j;
            used[best] = true; fidx[sel] = best;
        }
    }
    float nfsc[4]; int nffl[4]; int nfseq[4][MAXLEN_];
    for (int k = 0; k < 4; k++) {
        int j = fidx[k];
        nfsc[k] = cs[j]; nffl[k] = cfl[j];
        if (j < 4) {
            const int* sp = g_fin_seq + (b * BEAM_ + j) * MAXLEN_;
            for (int l = 0; l < MAXLEN_; l++) nfseq[k][l] = sp[l];
        } else {
            for (int l = 0; l < MAXLEN_; l++) nfseq[k][l] = tseq[j - 4][l];
        }
    }

    // --- write back
    for (int k = 0; k < 4; k++) {
        g_alive_lp[b * BEAM_ + k]   = nalp[k];
        g_fin_scores[b * BEAM_ + k] = nfsc[k];
        g_fin_flags[b * BEAM_ + k]  = nffl[k];
        for (int l = 0; l < MAXLEN_; l++) {
            g_alive_seq[(b * BEAM_ + k) * MAXLEN_ + l] = naseq[k][l];
            g_fin_seq[(b * BEAM_ + k) * MAXLEN_ + l]   = nfseq[k][l];
        }
    }

    // --- batch finished test
    float lb = __fdiv_rn(nalp[0], lpen);
    float lf = nfsc[0] * (nffl[0] ? 1.0f : 0.0f);
    for (int k = 1; k < 4; k++) lf = fminf(lf, nfsc[k] * (nffl[k] ? 1.0f : 0.0f));
    bool allf = nffl[0] && nffl[1] && nffl[2] && nffl[3];
    lf = lf + (allf ? 0.0f : -NEG_INF_PEN);
    if (lf >= lb) g_batch_fin[b] = 1;
}

// ------------------------------ output ---------------------------------------
__global__ void k_out(int* __restrict__ out) {
    int i = threadIdx.x;
    if (i < B_ * MAXLEN_) {
        int b = i / MAXLEN_, l = i % MAXLEN_;
        out[i] = g_fin_seq[(b * BEAM_ + 0) * MAXLEN_ + l];
    }
}

// ------------------------------ launcher -------------------------------------
extern "C" void kernel_launch(void* const* d_in, const int* in_sizes, int n_in,
                              void* d_out, int out_size) {
    (void)in_sizes; (void)n_in; (void)out_size;
    const int*   src  = (const int*)d_in[0];
    const float* Esrc = (const float*)d_in[1];
    const float* Etgt = (const float*)d_in[2];
    const float* W    = (const float*)d_in[3];
    const float* bias = (const float*)d_in[4];

    k_init<<<1, 1024>>>();
    k_pooled<<<B_, 256>>>(src, Esrc);

    for (int t = 0; t < MAXLEN_ - 1; t++) {
        k_prep<<<NR_, 128>>>(Etgt, t);
        k_gemm<<<V_ / 128, 256>>>(W, bias);
        k_rowstats<<<NR_, 256>>>();
        k_top8<<<B_, 256>>>(t);
        k_book<<<1, B_>>>(t);
    }
    k_out<<<1, 256>>>((int*)d_out);
}

// round 2
// speedup vs baseline: 1.6503x; 1.6503x over previous
#include <cuda_runtime.h>
#include <math.h>
#include <stdint.h>

// ---------------------------------------------------------------------------
// Beam search generator: B=16, BEAM=4, MAX_LEN=16, VOCAB=32000, D=512, S=128
// Inputs: src_input [16,128] i32, E_src [32000,512] f32, E_tgt [32000,512] f32,
//         W [512,32000] f32, b [32000] f32.  Output: fin_seq[:,0] -> [16,16] i32
// ---------------------------------------------------------------------------

#define B_      16
#define BEAM_   4
#define MAXLEN_ 16
#define V_      32000
#define D_      512
#define S_      128
#define NR_     64
#define NEG_INF_PEN 1e9f

// ------------------------------ device state --------------------------------
static __device__ __align__(16) float g_pooled[B_ * D_];
static __device__ __align__(16) float2 g_xT2[D_ * NR_];        // dup pairs: (x,x) at [k][row]
static __device__ __align__(16) float g_logits[(size_t)NR_ * V_];
static __device__ float g_alive_lp[B_ * BEAM_];
static __device__ int   g_alive_seq[B_ * BEAM_ * MAXLEN_];
static __device__ float g_fin_scores[B_ * BEAM_];
static __device__ int   g_fin_seq[B_ * BEAM_ * MAXLEN_];
static __device__ int   g_fin_flags[B_ * BEAM_];
static __device__ int   g_batch_fin[B_];
static __device__ unsigned long long g_cand[NR_ * 8];          // per-row top-8 keys

// ------------------------------ helpers -------------------------------------
__device__ __forceinline__ unsigned int ford(float f) {
    unsigned int u = __float_as_uint(f);
    return (u & 0x80000000u) ? ~u : (u | 0x80000000u);
}
__device__ __forceinline__ float finv(unsigned int u) {
    return __uint_as_float((u & 0x80000000u) ? (u ^ 0x80000000u) : ~u);
}
__device__ __forceinline__ unsigned long long umax64(unsigned long long a, unsigned long long b) {
    return a > b ? a : b;
}
// packed f32x2 FMA: d = a*b + d  (per-lane IEEE f32 FMA, bit-identical to FFMA)
__device__ __forceinline__ void ffma2(unsigned long long& d, unsigned long long a,
                                      unsigned long long b) {
    asm("fma.rn.f32x2 %0, %1, %2, %0;" : "+l"(d) : "l"(a), "l"(b));
}

// ------------------------------ init -----------------------------------------
__global__ void k_init() {
    int i = threadIdx.x;  // 1024 threads
    g_alive_seq[i] = ((i & (MAXLEN_ - 1)) == 0) ? 1 : 0;
    g_fin_seq[i] = 0;
    if (i < B_ * BEAM_) {
        g_alive_lp[i]   = ((i & (BEAM_ - 1)) == 0) ? 0.0f : -INFINITY;
        g_fin_scores[i] = -NEG_INF_PEN;
        g_fin_flags[i]  = 0;
    }
    if (i < B_) g_batch_fin[i] = 0;
}

// ------------------------------ encoder pooling ------------------------------
__global__ void __launch_bounds__(256) k_pooled(const int* __restrict__ src,
                                                const float* __restrict__ Esrc) {
    int b = blockIdx.x;
    int tid = threadIdx.x;
    __shared__ int toks[S_];
    if (tid < S_) toks[tid] = src[b * S_ + tid];
    __syncthreads();
    float cnt = 0.0f;
    for (int s = 0; s < S_; s++) cnt += (toks[s] != 0) ? 1.0f : 0.0f;
    float denom = fmaxf(cnt, 1.0f);
    for (int d = tid; d < D_; d += blockDim.x) {
        float acc = 0.0f;
        for (int s = 0; s < S_; s++) {
            int tk = toks[s];
            if (tk != 0) acc += Esrc[(size_t)tk * D_ + d];
        }
        g_pooled[b * D_ + d] = __fdiv_rn(acc, denom);
    }
}

// ------------------------------ x prep (writes dup pairs) --------------------
__global__ void k_prep(const float* __restrict__ Etgt, int t) {
    int r = blockIdx.x;            // 0..63
    int b = r >> 2;
    int tok = g_alive_seq[r * MAXLEN_ + t];
    const float* e = Etgt + (size_t)tok * D_;
    const float* p = g_pooled + b * D_;
    for (int k = threadIdx.x; k < D_; k += blockDim.x) {
        float v = e[k] + p[k];
        g_xT2[k * NR_ + r] = make_float2(v, v);
    }
}

// ------------------------------ SGEMM via fma.rn.f32x2 -----------------------
// logits[64][32000] = x @ W + bias.  Grid 125, block 256, tile 64M x 256N,
// micro-tile 8M x 8N paired along N. Double-buffered smem, Kc=8.
__global__ void __launch_bounds__(256, 1) k_gemm(const float* __restrict__ W,
                                                 const float* __restrict__ bias) {
    const int nb  = blockIdx.x * 256;
    const int tid = threadIdx.x;
    const int tni = tid & 31;   // N group (8 cols)
    const int tmi = tid >> 5;   // M group (8 rows)

    __shared__ float4      ws4[2][8][64];   // [buf][kk][256 floats]  (16 KB)
    __shared__ ulonglong2  xs2[2][8][32];   // [buf][kk][64 dup-pairs] (8 KB)

    unsigned long long acc[8][4];
#pragma unroll
    for (int i = 0; i < 8; i++)
#pragma unroll
        for (int j = 0; j < 4; j++) acc[i][j] = 0ull;

    const int kkW = tid >> 6, n4W = tid & 63;           // W copy coords (2 per thread)
    const int kkX = tid >> 4, qX = tid & 15;            // x copy coords (tid<128)

    float4 w0r, w1r, x0r;
    // prologue: chunk 0
    {
        const float* wsrc = W + (size_t)kkW * V_ + nb + n4W * 4;
        w0r = *reinterpret_cast<const float4*>(wsrc);
        w1r = *reinterpret_cast<const float4*>(wsrc + (size_t)4 * V_);
        if (tid < 128)
            x0r = *reinterpret_cast<const float4*>(&g_xT2[kkX * NR_ + qX * 2]);
        ws4[0][kkW][n4W] = w0r;
        ws4[0][kkW + 4][n4W] = w1r;
        if (tid < 128)
            *(reinterpret_cast<float4*>(&xs2[0][kkX][0]) + qX) = x0r;
    }
    __syncthreads();

    for (int c = 0; c < 64; c++) {
        const int buf = c & 1;
        if (c < 63) {
            const int k0 = (c + 1) * 8;
            const float* wsrc = W + (size_t)(k0 + kkW) * V_ + nb + n4W * 4;
            w0r = *reinterpret_cast<const float4*>(wsrc);
            w1r = *reinterpret_cast<const float4*>(wsrc + (size_t)4 * V_);
            if (tid < 128)
                x0r = *reinterpret_cast<const float4*>(&g_xT2[(k0 + kkX) * NR_ + qX * 2]);
        }
#pragma unroll
        for (int kk = 0; kk < 8; kk++) {
            const ulonglong2* xp = &xs2[buf][kk][tmi * 4];
            const ulonglong2* wp = reinterpret_cast<const ulonglong2*>(&ws4[buf][kk][tni * 2]);
            ulonglong2 B0 = wp[0];
            ulonglong2 B1 = wp[1];
#pragma unroll
            for (int q = 0; q < 4; q++) {
                ulonglong2 A = xp[q];
                ffma2(acc[2 * q][0],     A.x, B0.x);
                ffma2(acc[2 * q][1],     A.x, B0.y);
                ffma2(acc[2 * q][2],     A.x, B1.x);
                ffma2(acc[2 * q][3],     A.x, B1.y);
                ffma2(acc[2 * q + 1][0], A.y, B0.x);
                ffma2(acc[2 * q + 1][1], A.y, B0.y);
                ffma2(acc[2 * q + 1][2], A.y, B1.x);
                ffma2(acc[2 * q + 1][3], A.y, B1.y);
            }
        }
        if (c < 63) {
            const int nbuf = buf ^ 1;
            ws4[nbuf][kkW][n4W] = w0r;
            ws4[nbuf][kkW + 4][n4W] = w1r;
            if (tid < 128)
                *(reinterpret_cast<float4*>(&xs2[nbuf][kkX][0]) + qX) = x0r;
            __syncthreads();
        }
    }

    // epilogue
    const int col0 = nb + tni * 8;
    float4 bza = *reinterpret_cast<const float4*>(bias + col0);
    float4 bzb = *reinterpret_cast<const float4*>(bias + col0 + 4);
#pragma unroll
    for (int i = 0; i < 8; i++) {
        int row = tmi * 8 + i;
        float2 p0 = *reinterpret_cast<float2*>(&acc[i][0]);
        float2 p1 = *reinterpret_cast<float2*>(&acc[i][1]);
        float2 p2 = *reinterpret_cast<float2*>(&acc[i][2]);
        float2 p3 = *reinterpret_cast<float2*>(&acc[i][3]);
        float4 o0 = make_float4(p0.x + bza.x, p0.y + bza.y, p1.x + bza.z, p1.y + bza.w);
        float4 o1 = make_float4(p2.x + bzb.x, p2.y + bzb.y, p3.x + bzb.z, p3.y + bzb.w);
        *reinterpret_cast<float4*>(g_logits + (size_t)row * V_ + col0) = o0;
        *reinterpret_cast<float4*>(g_logits + (size_t)row * V_ + col0 + 4) = o1;
    }
}

// ------------------------------ fused logsumexp + per-row top-8 --------------
__global__ void __launch_bounds__(256) k_score(int t) {
    int r = blockIdx.x, tid = threadIdx.x;
    const float* lrow = g_logits + (size_t)r * V_;

    // pass 1: online logsumexp (identical structure/numerics to R1 k_rowstats)
    float m = -INFINITY, s = 0.0f;
    for (int v = tid; v < V_; v += 256) {
        float x = lrow[v];
        if (x > m) { s = s * expf(m - x) + 1.0f; m = x; }
        else       { s += expf(x - m); }
    }
    __shared__ float sm[256], ss[256];
    sm[tid] = m; ss[tid] = s;
    __syncthreads();
    for (int off = 128; off > 0; off >>= 1) {
        if (tid < off) {
            float m1 = sm[tid], s1 = ss[tid];
            float m2 = sm[tid + off], s2 = ss[tid + off];
            if (m2 > m1) { sm[tid] = m2; ss[tid] = s1 * expf(m1 - m2) + s2; }
            else         { ss[tid] = s1 + s2 * expf(m2 - m1); }
        }
        __syncthreads();
    }
    __shared__ float rmz[2];
    if (tid == 0) { rmz[0] = sm[0]; rmz[1] = logf(ss[0]); }
    __syncthreads();
    float rm = rmz[0], rz = rmz[1];

    // pass 2: per-thread top-8 under key (ford(s)<<32 | ~flatidx)
    float al = g_alive_lp[r];
    float lpen = (float)(t + 1);
    unsigned int beamBase = (unsigned int)((r & 3) * V_);
    unsigned long long loc[8];
#pragma unroll
    for (int i = 0; i < 8; i++) loc[i] = 0ull;
    for (int v = tid; v < V_; v += 256) {
        float lp = (lrow[v] - rm) - rz;
        float sc = __fdiv_rn(al + lp, lpen);
        unsigned long long key = ((unsigned long long)ford(sc) << 32)
                               | (unsigned long long)(0xFFFFFFFFu - (beamBase + v));
        if (key > loc[7]) {
            loc[7] = key;
#pragma unroll
            for (int i = 7; i > 0; i--) {
                if (loc[i] > loc[i - 1]) {
                    unsigned long long tmp = loc[i]; loc[i] = loc[i - 1]; loc[i - 1] = tmp;
                }
            }
        }
    }

    __shared__ unsigned long long pool[256 * 8];
    __shared__ unsigned long long red[256];
#pragma unroll
    for (int i = 0; i < 8; i++) pool[tid * 8 + i] = loc[i];
    __syncthreads();
    for (int sel = 0; sel < 8; sel++) {
        unsigned long long mx = 0ull;
#pragma unroll
        for (int i = 0; i < 8; i++) mx = umax64(mx, pool[tid * 8 + i]);
        red[tid] = mx;
        __syncthreads();
        for (int off = 128; off > 0; off >>= 1) {
            if (tid < off) red[tid] = umax64(red[tid], red[tid + off]);
            __syncthreads();
        }
        unsigned long long w = red[0];
#pragma unroll
        for (int i = 0; i < 8; i++)
            if (pool[tid * 8 + i] == w) pool[tid * 8 + i] = 0ull;  // keys unique
        if (tid == 0) g_cand[r * 8 + sel] = w;
        __syncthreads();
    }
}

// ------------------------------ beam bookkeeping (1 thread / batch) ----------
__global__ void k_book(int t) {
    int b = threadIdx.x;
    if (b >= B_) return;
    float lpen = (float)(t + 1);

    // merge 4 rows x 8 candidates -> batch top-8 (exact global key order)
    unsigned long long cand[32];
    for (int j = 0; j < 32; j++) cand[j] = g_cand[(b * BEAM_) * 8 + j];

    float sc[8]; int id[8];
    {
        bool used[32] = {};
        for (int sel = 0; sel < 8; sel++) {
            int best = -1;
            unsigned long long bk = 0ull;
            for (int j = 0; j < 32; j++)
                if (!used[j] && cand[j] >= bk) {
                    // strict max; keys unique so >= only matters vs init 0
                    if (cand[j] > bk || best < 0) { bk = cand[j]; best = j; }
                }
            used[best] = true;
            sc[sel] = finv((unsigned int)(bk >> 32));
            id[sel] = (int)(0xFFFFFFFFu - (unsigned int)bk);
        }
    }

    int tok[8], bix[8], fin[8]; float tlp[8];
    for (int j = 0; j < 8; j++) {
        tok[j] = id[j] % V_;
        bix[j] = (t == 0) ? (j & 3) : (id[j] / V_);
        fin[j] = (tok[j] == 2);
        tlp[j] = sc[j] * lpen;
    }

    int tseq[8][MAXLEN_];
    for (int j = 0; j < 8; j++) {
        const int* sp = g_alive_seq + (b * BEAM_ + bix[j]) * MAXLEN_;
        for (int l = 0; l < MAXLEN_; l++) tseq[j][l] = sp[l];
        tseq[j][t + 1] = tok[j];
    }

    // alive set: top-4 of (score + fin * -1e9), lowest index wins ties
    float curr[8];
    for (int j = 0; j < 8; j++) curr[j] = sc[j] + (fin[j] ? -NEG_INF_PEN : 0.0f);
    int aidx[4];
    {
        bool used[8] = {};
        for (int sel = 0; sel < 4; sel++) {
            int best = -1;
            for (int j = 0; j < 8; j++)
                if (!used[j] && (best < 0 || curr[j] > curr[best])) best = j;
            used[best] = true; aidx[sel] = best;
        }
    }
    float nalp[4]; int naseq[4][MAXLEN_];
    for (int k = 0; k < 4; k++) {
        nalp[k] = tlp[aidx[k]];
        for (int l = 0; l < MAXLEN_; l++) naseq[k][l] = tseq[aidx[k]][l];
    }

    // finished set
    float bfp = g_batch_fin[b] ? -NEG_INF_PEN : 0.0f;
    float cs[12]; int cfl[12];
    for (int k = 0; k < 4; k++) {
        cs[k]  = g_fin_scores[b * BEAM_ + k];
        cfl[k] = g_fin_flags[b * BEAM_ + k];
    }
    for (int j = 0; j < 8; j++) {
        cs[4 + j]  = (sc[j] + (fin[j] ? 0.0f : -NEG_INF_PEN)) + bfp;
        cfl[4 + j] = fin[j];
    }
    int fidx[4];
    {
        bool used[12] = {};
        for (int sel = 0; sel < 4; sel++) {
            int best = -1;
            for (int j = 0; j < 12; j++)
                if (!used[j] && (best < 0 || cs[j] > cs[best])) best = j;
            used[best] = true; fidx[sel] = best;
        }
    }
    float nfsc[4]; int nffl[4]; int nfseq[4][MAXLEN_];
    for (int k = 0; k < 4; k++) {
        int j = fidx[k];
        nfsc[k] = cs[j]; nffl[k] = cfl[j];
        if (j < 4) {
            const int* sp = g_fin_seq + (b * BEAM_ + j) * MAXLEN_;
            for (int l = 0; l < MAXLEN_; l++) nfseq[k][l] = sp[l];
        } else {
            for (int l = 0; l < MAXLEN_; l++) nfseq[k][l] = tseq[j - 4][l];
        }
    }

    for (int k = 0; k < 4; k++) {
        g_alive_lp[b * BEAM_ + k]   = nalp[k];
        g_fin_scores[b * BEAM_ + k] = nfsc[k];
        g_fin_flags[b * BEAM_ + k]  = nffl[k];
        for (int l = 0; l < MAXLEN_; l++) {
            g_alive_seq[(b * BEAM_ + k) * MAXLEN_ + l] = naseq[k][l];
            g_fin_seq[(b * BEAM_ + k) * MAXLEN_ + l]   = nfseq[k][l];
        }
    }

    float lb = __fdiv_rn(nalp[0], lpen);
    float lf = nfsc[0] * (nffl[0] ? 1.0f : 0.0f);
    for (int k = 1; k < 4; k++) lf = fminf(lf, nfsc[k] * (nffl[k] ? 1.0f : 0.0f));
    bool allf = nffl[0] && nffl[1] && nffl[2] && nffl[3];
    lf = lf + (allf ? 0.0f : -NEG_INF_PEN);
    if (lf >= lb) g_batch_fin[b] = 1;
}

// ------------------------------ output ---------------------------------------
__global__ void k_out(int* __restrict__ out) {
    int i = threadIdx.x;
    if (i < B_ * MAXLEN_) {
        int b = i / MAXLEN_, l = i % MAXLEN_;
        out[i] = g_fin_seq[(b * BEAM_ + 0) * MAXLEN_ + l];
    }
}

// ------------------------------ launcher -------------------------------------
extern "C" void kernel_launch(void* const* d_in, const int* in_sizes, int n_in,
                              void* d_out, int out_size) {
    (void)in_sizes; (void)n_in; (void)out_size;
    const int*   src  = (const int*)d_in[0];
    const float* Esrc = (const float*)d_in[1];
    const float* Etgt = (const float*)d_in[2];
    const float* W    = (const float*)d_in[3];
    const float* bias = (const float*)d_in[4];

    k_init<<<1, 1024>>>();
    k_pooled<<<B_, 256>>>(src, Esrc);

    for (int t = 0; t < MAXLEN_ - 1; t++) {
        k_prep<<<NR_, 128>>>(Etgt, t);
        k_gemm<<<V_ / 256, 256>>>(W, bias);
        k_score<<<NR_, 256>>>(t);
        k_book<<<1, B_>>>(t);
    }
    k_out<<<1, 256>>>((int*)d_out);
}

// round 3
// speedup vs baseline: 1.6588x; 1.0051x over previous
#include <cuda_runtime.h>
#include <math.h>
#include <stdint.h>

// ---------------------------------------------------------------------------
// Beam search generator: B=16, BEAM=4, MAX_LEN=16, VOCAB=32000, D=512, S=128
// Inputs: src_input [16,128] i32, E_src [32000,512] f32, E_tgt [32000,512] f32,
//         W [512,32000] f32, b [32000] f32.  Output: fin_seq[:,0] -> [16,16] i32
// ---------------------------------------------------------------------------

#define B_      16
#define BEAM_   4
#define MAXLEN_ 16
#define V_      32000
#define D_      512
#define S_      128
#define NR_     64
#define NEG_INF_PEN 1e9f

// ------------------------------ device state --------------------------------
static __device__ __align__(16) float g_pooled[B_ * D_];
static __device__ __align__(16) float2 g_xT2[D_ * NR_];        // dup pairs: (x,x) at [k][row]
static __device__ __align__(16) float g_logits[(size_t)NR_ * V_];
static __device__ float g_alive_lp[B_ * BEAM_];
static __device__ int   g_alive_seq[B_ * BEAM_ * MAXLEN_];
static __device__ float g_fin_scores[B_ * BEAM_];
static __device__ int   g_fin_seq[B_ * BEAM_ * MAXLEN_];
static __device__ int   g_fin_flags[B_ * BEAM_];
static __device__ int   g_batch_fin[B_];
static __device__ unsigned long long g_cand[NR_ * 8];          // per-row top-8 keys

// ------------------------------ helpers -------------------------------------
__device__ __forceinline__ unsigned int ford(float f) {
    unsigned int u = __float_as_uint(f);
    return (u & 0x80000000u) ? ~u : (u | 0x80000000u);
}
__device__ __forceinline__ float finv(unsigned int u) {
    return __uint_as_float((u & 0x80000000u) ? (u ^ 0x80000000u) : ~u);
}
__device__ __forceinline__ unsigned long long umax64(unsigned long long a, unsigned long long b) {
    return a > b ? a : b;
}
// packed f32x2 FMA: d = a*b + d  (per-lane IEEE f32 FMA, bit-identical to FFMA)
__device__ __forceinline__ void ffma2(unsigned long long& d, unsigned long long a,
                                      unsigned long long b) {
    asm("fma.rn.f32x2 %0, %1, %2, %0;" : "+l"(d) : "l"(a), "l"(b));
}

// ------------------------------ init -----------------------------------------
__global__ void k_init() {
    int i = threadIdx.x;  // 1024 threads
    g_alive_seq[i] = ((i & (MAXLEN_ - 1)) == 0) ? 1 : 0;
    g_fin_seq[i] = 0;
    if (i < B_ * BEAM_) {
        g_alive_lp[i]   = ((i & (BEAM_ - 1)) == 0) ? 0.0f : -INFINITY;
        g_fin_scores[i] = -NEG_INF_PEN;
        g_fin_flags[i]  = 0;
    }
    if (i < B_) g_batch_fin[i] = 0;
}

// ------------------------------ encoder pooling ------------------------------
__global__ void __launch_bounds__(256) k_pooled(const int* __restrict__ src,
                                                const float* __restrict__ Esrc) {
    int b = blockIdx.x;
    int tid = threadIdx.x;
    __shared__ int toks[S_];
    if (tid < S_) toks[tid] = src[b * S_ + tid];
    __syncthreads();
    float cnt = 0.0f;
    for (int s = 0; s < S_; s++) cnt += (toks[s] != 0) ? 1.0f : 0.0f;
    float denom = fmaxf(cnt, 1.0f);
    for (int d = tid; d < D_; d += blockDim.x) {
        float acc = 0.0f;
        for (int s = 0; s < S_; s++) {
            int tk = toks[s];
            if (tk != 0) acc += Esrc[(size_t)tk * D_ + d];
        }
        g_pooled[b * D_ + d] = __fdiv_rn(acc, denom);
    }
}

// ------------------------------ x prep (writes dup pairs) --------------------
__global__ void k_prep(const float* __restrict__ Etgt, int t) {
    int r = blockIdx.x;            // 0..63
    int b = r >> 2;
    int tok = g_alive_seq[r * MAXLEN_ + t];
    const float* e = Etgt + (size_t)tok * D_;
    const float* p = g_pooled + b * D_;
    for (int k = threadIdx.x; k < D_; k += blockDim.x) {
        float v = e[k] + p[k];
        g_xT2[k * NR_ + r] = make_float2(v, v);
    }
}

// ------------------------------ SGEMM via fma.rn.f32x2 -----------------------
// logits[64][32000] = x @ W + bias.  Grid 125, block 256, tile 64M x 256N,
// micro-tile 8M x 8N paired along N. Double-buffered smem, Kc=8.
__global__ void __launch_bounds__(256, 1) k_gemm(const float* __restrict__ W,
                                                 const float* __restrict__ bias) {
    const int nb  = blockIdx.x * 256;
    const int tid = threadIdx.x;
    const int tni = tid & 31;   // N group (8 cols)
    const int tmi = tid >> 5;   // M group (8 rows)

    __shared__ float4      ws4[2][8][64];   // [buf][kk][256 floats]  (16 KB)
    __shared__ ulonglong2  xs2[2][8][32];   // [buf][kk][64 dup-pairs] (8 KB)

    unsigned long long acc[8][4];
#pragma unroll
    for (int i = 0; i < 8; i++)
#pragma unroll
        for (int j = 0; j < 4; j++) acc[i][j] = 0ull;

    const int kkW = tid >> 6, n4W = tid & 63;           // W copy coords (2 per thread)
    const int kkX = tid >> 4, qX = tid & 15;            // x copy coords (tid<128)

    float4 w0r, w1r, x0r;
    // prologue: chunk 0
    {
        const float* wsrc = W + (size_t)kkW * V_ + nb + n4W * 4;
        w0r = *reinterpret_cast<const float4*>(wsrc);
        w1r = *reinterpret_cast<const float4*>(wsrc + (size_t)4 * V_);
        if (tid < 128)
            x0r = *reinterpret_cast<const float4*>(&g_xT2[kkX * NR_ + qX * 2]);
        ws4[0][kkW][n4W] = w0r;
        ws4[0][kkW + 4][n4W] = w1r;
        if (tid < 128)
            *(reinterpret_cast<float4*>(&xs2[0][kkX][0]) + qX) = x0r;
    }
    __syncthreads();

    for (int c = 0; c < 64; c++) {
        const int buf = c & 1;
        if (c < 63) {
            const int k0 = (c + 1) * 8;
            const float* wsrc = W + (size_t)(k0 + kkW) * V_ + nb + n4W * 4;
            w0r = *reinterpret_cast<const float4*>(wsrc);
            w1r = *reinterpret_cast<const float4*>(wsrc + (size_t)4 * V_);
            if (tid < 128)
                x0r = *reinterpret_cast<const float4*>(&g_xT2[(k0 + kkX) * NR_ + qX * 2]);
        }
#pragma unroll
        for (int kk = 0; kk < 8; kk++) {
            const ulonglong2* xp = &xs2[buf][kk][tmi * 4];
            const ulonglong2* wp = reinterpret_cast<const ulonglong2*>(&ws4[buf][kk][tni * 2]);
            ulonglong2 B0 = wp[0];
            ulonglong2 B1 = wp[1];
#pragma unroll
            for (int q = 0; q < 4; q++) {
                ulonglong2 A = xp[q];
                ffma2(acc[2 * q][0],     A.x, B0.x);
                ffma2(acc[2 * q][1],     A.x, B0.y);
                ffma2(acc[2 * q][2],     A.x, B1.x);
                ffma2(acc[2 * q][3],     A.x, B1.y);
                ffma2(acc[2 * q + 1][0], A.y, B0.x);
                ffma2(acc[2 * q + 1][1], A.y, B0.y);
                ffma2(acc[2 * q + 1][2], A.y, B1.x);
                ffma2(acc[2 * q + 1][3], A.y, B1.y);
            }
        }
        if (c < 63) {
            const int nbuf = buf ^ 1;
            ws4[nbuf][kkW][n4W] = w0r;
            ws4[nbuf][kkW + 4][n4W] = w1r;
            if (tid < 128)
                *(reinterpret_cast<float4*>(&xs2[nbuf][kkX][0]) + qX) = x0r;
            __syncthreads();
        }
    }

    // epilogue
    const int col0 = nb + tni * 8;
    float4 bza = *reinterpret_cast<const float4*>(bias + col0);
    float4 bzb = *reinterpret_cast<const float4*>(bias + col0 + 4);
#pragma unroll
    for (int i = 0; i < 8; i++) {
        int row = tmi * 8 + i;
        float2 p0 = *reinterpret_cast<float2*>(&acc[i][0]);
        float2 p1 = *reinterpret_cast<float2*>(&acc[i][1]);
        float2 p2 = *reinterpret_cast<float2*>(&acc[i][2]);
        float2 p3 = *reinterpret_cast<float2*>(&acc[i][3]);
        float4 o0 = make_float4(p0.x + bza.x, p0.y + bza.y, p1.x + bza.z, p1.y + bza.w);
        float4 o1 = make_float4(p2.x + bzb.x, p2.y + bzb.y, p3.x + bzb.z, p3.y + bzb.w);
        *reinterpret_cast<float4*>(g_logits + (size_t)row * V_ + col0) = o0;
        *reinterpret_cast<float4*>(g_logits + (size_t)row * V_ + col0 + 4) = o1;
    }
}

// ------------------------------ fused logsumexp + per-row top-8 --------------
__global__ void __launch_bounds__(256) k_score(int t) {
    int r = blockIdx.x, tid = threadIdx.x;
    const float* lrow = g_logits + (size_t)r * V_;

    // pass 1: online logsumexp (identical structure/numerics to R1 k_rowstats)
    float m = -INFINITY, s = 0.0f;
    for (int v = tid; v < V_; v += 256) {
        float x = lrow[v];
        if (x > m) { s = s * expf(m - x) + 1.0f; m = x; }
        else       { s += expf(x - m); }
    }
    __shared__ float sm[256], ss[256];
    sm[tid] = m; ss[tid] = s;
    __syncthreads();
    for (int off = 128; off > 0; off >>= 1) {
        if (tid < off) {
            float m1 = sm[tid], s1 = ss[tid];
            float m2 = sm[tid + off], s2 = ss[tid + off];
            if (m2 > m1) { sm[tid] = m2; ss[tid] = s1 * expf(m1 - m2) + s2; }
            else         { ss[tid] = s1 + s2 * expf(m2 - m1); }
        }
        __syncthreads();
    }
    __shared__ float rmz[2];
    if (tid == 0) { rmz[0] = sm[0]; rmz[1] = logf(ss[0]); }
    __syncthreads();
    float rm = rmz[0], rz = rmz[1];

    // pass 2: per-thread top-8 under key (ford(s)<<32 | ~flatidx)
    float al = g_alive_lp[r];
    float lpen = (float)(t + 1);
    unsigned int beamBase = (unsigned int)((r & 3) * V_);
    unsigned long long loc[8];
#pragma unroll
    for (int i = 0; i < 8; i++) loc[i] = 0ull;
    for (int v = tid; v < V_; v += 256) {
        float lp = (lrow[v] - rm) - rz;
        float sc = __fdiv_rn(al + lp, lpen);
        unsigned long long key = ((unsigned long long)ford(sc) << 32)
                               | (unsigned long long)(0xFFFFFFFFu - (beamBase + v));
        if (key > loc[7]) {
            loc[7] = key;
#pragma unroll
            for (int i = 7; i > 0; i--) {
                if (loc[i] > loc[i - 1]) {
                    unsigned long long tmp = loc[i]; loc[i] = loc[i - 1]; loc[i - 1] = tmp;
                }
            }
        }
    }

    __shared__ unsigned long long pool[256 * 8];
    __shared__ unsigned long long red[256];
#pragma unroll
    for (int i = 0; i < 8; i++) pool[tid * 8 + i] = loc[i];
    __syncthreads();
    for (int sel = 0; sel < 8; sel++) {
        unsigned long long mx = 0ull;
#pragma unroll
        for (int i = 0; i < 8; i++) mx = umax64(mx, pool[tid * 8 + i]);
        red[tid] = mx;
        __syncthreads();
        for (int off = 128; off > 0; off >>= 1) {
            if (tid < off) red[tid] = umax64(red[tid], red[tid + off]);
            __syncthreads();
        }
        unsigned long long w = red[0];
#pragma unroll
        for (int i = 0; i < 8; i++)
            if (pool[tid * 8 + i] == w) pool[tid * 8 + i] = 0ull;  // keys unique
        if (tid == 0) g_cand[r * 8 + sel] = w;
        __syncthreads();
    }
}

// ------------------------------ beam bookkeeping (1 thread / batch) ----------
__global__ void k_book(int t) {
    int b = threadIdx.x;
    if (b >= B_) return;
    float lpen = (float)(t + 1);

    // merge 4 rows x 8 candidates -> batch top-8 (exact global key order)
    unsigned long long cand[32];
    for (int j = 0; j < 32; j++) cand[j] = g_cand[(b * BEAM_) * 8 + j];

    float sc[8]; int id[8];
    {
        bool used[32] = {};
        for (int sel = 0; sel < 8; sel++) {
            int best = -1;
            unsigned long long bk = 0ull;
            for (int j = 0; j < 32; j++)
                if (!used[j] && cand[j] >= bk) {
                    // strict max; keys unique so >= only matters vs init 0
                    if (cand[j] > bk || best < 0) { bk = cand[j]; best = j; }
                }
            used[best] = true;
            sc[sel] = finv((unsigned int)(bk >> 32));
            id[sel] = (int)(0xFFFFFFFFu - (unsigned int)bk);
        }
    }

    int tok[8], bix[8], fin[8]; float tlp[8];
    for (int j = 0; j < 8; j++) {
        tok[j] = id[j] % V_;
        bix[j] = (t == 0) ? (j & 3) : (id[j] / V_);
        fin[j] = (tok[j] == 2);
        tlp[j] = sc[j] * lpen;
    }

    int tseq[8][MAXLEN_];
    for (int j = 0; j < 8; j++) {
        const int* sp = g_alive_seq + (b * BEAM_ + bix[j]) * MAXLEN_;
        for (int l = 0; l < MAXLEN_; l++) tseq[j][l] = sp[l];
        tseq[j][t + 1] = tok[j];
    }

    // alive set: top-4 of (score + fin * -1e9), lowest index wins ties
    float curr[8];
    for (int j = 0; j < 8; j++) curr[j] = sc[j] + (fin[j] ? -NEG_INF_PEN : 0.0f);
    int aidx[4];
    {
        bool used[8] = {};
        for (int sel = 0; sel < 4; sel++) {
            int best = -1;
            for (int j = 0; j < 8; j++)
                if (!used[j] && (best < 0 || curr[j] > curr[best])) best = j;
            used[best] = true; aidx[sel] = best;
        }
    }
    float nalp[4]; int naseq[4][MAXLEN_];
    for (int k = 0; k < 4; k++) {
        nalp[k] = tlp[aidx[k]];
        for (int l = 0; l < MAXLEN_; l++) naseq[k][l] = tseq[aidx[k]][l];
    }

    // finished set
    float bfp = g_batch_fin[b] ? -NEG_INF_PEN : 0.0f;
    float cs[12]; int cfl[12];
    for (int k = 0; k < 4; k++) {
        cs[k]  = g_fin_scores[b * BEAM_ + k];
        cfl[k] = g_fin_flags[b * BEAM_ + k];
    }
    for (int j = 0; j < 8; j++) {
        cs[4 + j]  = (sc[j] + (fin[j] ? 0.0f : -NEG_INF_PEN)) + bfp;
        cfl[4 + j] = fin[j];
    }
    int fidx[4];
    {
        bool used[12] = {};
        for (int sel = 0; sel < 4; sel++) {
            int best = -1;
            for (int j = 0; j < 12; j++)
                if (!used[j] && (best < 0 || cs[j] > cs[best])) best = j;
            used[best] = true; fidx[sel] = best;
        }
    }
    float nfsc[4]; int nffl[4]; int nfseq[4][MAXLEN_];
    for (int k = 0; k < 4; k++) {
        int j = fidx[k];
        nfsc[k] = cs[j]; nffl[k] = cfl[j];
        if (j < 4) {
            const int* sp = g_fin_seq + (b * BEAM_ + j) * MAXLEN_;
            for (int l = 0; l < MAXLEN_; l++) nfseq[k][l] = sp[l];
        } else {
            for (int l = 0; l < MAXLEN_; l++) nfseq[k][l] = tseq[j - 4][l];
        }
    }

    for (int k = 0; k < 4; k++) {
        g_alive_lp[b * BEAM_ + k]   = nalp[k];
        g_fin_scores[b * BEAM_ + k] = nfsc[k];
        g_fin_flags[b * BEAM_ + k]  = nffl[k];
        for (int l = 0; l < MAXLEN_; l++) {
            g_alive_seq[(b * BEAM_ + k) * MAXLEN_ + l] = naseq[k][l];
            g_fin_seq[(b * BEAM_ + k) * MAXLEN_ + l]   = nfseq[k][l];
        }
    }

    float lb = __fdiv_rn(nalp[0], lpen);
    float lf = nfsc[0] * (nffl[0] ? 1.0f : 0.0f);
    for (int k = 1; k < 4; k++) lf = fminf(lf, nfsc[k] * (nffl[k] ? 1.0f : 0.0f));
    bool allf = nffl[0] && nffl[1] && nffl[2] && nffl[3];
    lf = lf + (allf ? 0.0f : -NEG_INF_PEN);
    if (lf >= lb) g_batch_fin[b] = 1;
}

// ------------------------------ output ---------------------------------------
__global__ void k_out(int* __restrict__ out) {
    int i = threadIdx.x;
    if (i < B_ * MAXLEN_) {
        int b = i / MAXLEN_, l = i % MAXLEN_;
        out[i] = g_fin_seq[(b * BEAM_ + 0) * MAXLEN_ + l];
    }
}

// ------------------------------ launcher -------------------------------------
extern "C" void kernel_launch(void* const* d_in, const int* in_sizes, int n_in,
                              void* d_out, int out_size) {
    (void)in_sizes; (void)n_in; (void)out_size;
    const int*   src  = (const int*)d_in[0];
    const float* Esrc = (const float*)d_in[1];
    const float* Etgt = (const float*)d_in[2];
    const float* W    = (const float*)d_in[3];
    const float* bias = (const float*)d_in[4];

    k_init<<<1, 1024>>>();
    k_pooled<<<B_, 256>>>(src, Esrc);

    for (int t = 0; t < MAXLEN_ - 1; t++) {
        k_prep<<<NR_, 128>>>(Etgt, t);
        k_gemm<<<V_ / 256, 256>>>(W, bias);
        k_score<<<NR_, 256>>>(t);
        k_book<<<1, B_>>>(t);
    }
    k_out<<<1, 256>>>((int*)d_out);
}

// round 5
// speedup vs baseline: 1.7847x; 1.0759x over previous
#include <cuda_runtime.h>
#include <cuda_bf16.h>
#include <math.h>
#include <stdint.h>

// ---------------------------------------------------------------------------
// Beam search generator: B=16, BEAM=4, MAX_LEN=16, VOCAB=32000, D=512, S=128
// GEMM via mma.sync bf16x3 split (fp32-grade accuracy on tensor cores,
// baseline sm_80 PTX -- no tcgen05, which the harness's compute_103 target
// rejects).
// ---------------------------------------------------------------------------

#define B_      16
#define BEAM_   4
#define MAXLEN_ 16
#define V_      32000
#define D_      512
#define S_      128
#define NR_     64
#define NEG_INF_PEN 1e9f

#define WSZ     (V_ * D_)          // 16,384,000 elements per W split
#define XSZ     (NR_ * D_)         // 32,768 elements per x split

// ------------------------------ device state --------------------------------
static __device__ __align__(16) float g_pooled[B_ * D_];
static __device__ __align__(16) __nv_bfloat16 g_Wsp[3 * WSZ];   // W splits, [s][n][k]
static __device__ __align__(16) __nv_bfloat16 g_xsp[3 * XSZ];   // x splits, [s][r][k]
static __device__ __align__(16) float g_logits[(size_t)NR_ * V_];
static __device__ float g_alive_lp[B_ * BEAM_];
static __device__ int   g_alive_seq[B_ * BEAM_ * MAXLEN_];
static __device__ float g_fin_scores[B_ * BEAM_];
static __device__ int   g_fin_seq[B_ * BEAM_ * MAXLEN_];
static __device__ int   g_fin_flags[B_ * BEAM_];
static __device__ int   g_batch_fin[B_];
static __device__ unsigned long long g_cand[NR_ * 8];

// ------------------------------ generic helpers ------------------------------
__device__ __forceinline__ unsigned int ford(float f) {
    unsigned int u = __float_as_uint(f);
    return (u & 0x80000000u) ? ~u : (u | 0x80000000u);
}
__device__ __forceinline__ float finv(unsigned int u) {
    return __uint_as_float((u & 0x80000000u) ? (u ^ 0x80000000u) : ~u);
}
__device__ __forceinline__ unsigned long long umax64(unsigned long long a, unsigned long long b) {
    return a > b ? a : b;
}
// exp(u) for u in [-0.25, 0] on the FMA pipe; rel err < 2e-8. MUFU fallback else.
__device__ __forceinline__ float pexp(float u) {
    if (u < -0.25f) return __expf(u);
    float p = fmaf(u, 1.0f / 720.0f, 1.0f / 120.0f);
    p = fmaf(u, p, 1.0f / 24.0f);
    p = fmaf(u, p, 1.0f / 6.0f);
    p = fmaf(u, p, 0.5f);
    p = fmaf(u, p, 1.0f);
    p = fmaf(u, p, 1.0f);
    return p;
}

// ------------------------------ PTX helpers (sm_80 baseline) -----------------
__device__ __forceinline__ uint32_t smem_u32(const void* p) {
    uint32_t a;
    asm("{ .reg .u64 t; cvta.to.shared.u64 t, %1; cvt.u32.u64 %0, t; }" : "=r"(a) : "l"(p));
    return a;
}
__device__ __forceinline__ void cp16(uint32_t dst, const void* src) {
    asm volatile("{ .reg .u64 g; cvta.to.global.u64 g, %1;\n\t"
                 "cp.async.cg.shared.global [%0], [g], 16; }"
                 :: "r"(dst), "l"(src) : "memory");
}
#define CP_COMMIT() asm volatile("cp.async.commit_group;" ::: "memory")
#define CP_WAIT1()  asm volatile("cp.async.wait_group 1;" ::: "memory")

#define LDMX4(r0, r1, r2, r3, addr) \
    asm volatile("ldmatrix.sync.aligned.m8n8.x4.shared.b16 {%0,%1,%2,%3}, [%4];" \
                 : "=r"(r0), "=r"(r1), "=r"(r2), "=r"(r3) : "r"(addr))

#define MMA16816(d, a, b0r, b1r) \
    asm volatile("mma.sync.aligned.m16n8k16.row.col.f32.bf16.bf16.f32 " \
                 "{%0,%1,%2,%3}, {%4,%5,%6,%7}, {%8,%9}, {%0,%1,%2,%3};" \
                 : "+f"((d)[0]), "+f"((d)[1]), "+f"((d)[2]), "+f"((d)[3]) \
                 : "r"((a)[0]), "r"((a)[1]), "r"((a)[2]), "r"((a)[3]), \
                   "r"(b0r), "r"(b1r))

// ------------------------------ init -----------------------------------------
__global__ void k_init() {
    int i = threadIdx.x;
    g_alive_seq[i] = ((i & (MAXLEN_ - 1)) == 0) ? 1 : 0;
    g_fin_seq[i] = 0;
    if (i < B_ * BEAM_) {
        g_alive_lp[i]   = ((i & (BEAM_ - 1)) == 0) ? 0.0f : -INFINITY;
        g_fin_scores[i] = -NEG_INF_PEN;
        g_fin_flags[i]  = 0;
    }
    if (i < B_) g_batch_fin[i] = 0;
}

// ------------------------------ encoder pooling ------------------------------
__global__ void __launch_bounds__(256) k_pooled(const int* __restrict__ src,
                                                const float* __restrict__ Esrc) {
    int b = blockIdx.x;
    int tid = threadIdx.x;
    __shared__ int toks[S_];
    if (tid < S_) toks[tid] = src[b * S_ + tid];
    __syncthreads();
    float cnt = 0.0f;
    for (int s = 0; s < S_; s++) cnt += (toks[s] != 0) ? 1.0f : 0.0f;
    float denom = fmaxf(cnt, 1.0f);
    for (int d = tid; d < D_; d += blockDim.x) {
        float acc = 0.0f;
        for (int s = 0; s < S_; s++) {
            int tk = toks[s];
            if (tk != 0) acc += Esrc[(size_t)tk * D_ + d];
        }
        g_pooled[b * D_ + d] = __fdiv_rn(acc, denom);
    }
}

// ------------------------------ W split + transpose (once per call) ----------
__global__ void __launch_bounds__(256) k_wprep(const float* __restrict__ W) {
    int ktile = blockIdx.x & 7;       // 8 tiles of 64 along K
    int ntile = blockIdx.x >> 3;      // 500 tiles of 64 along N
    int k0 = ktile * 64, n0 = ntile * 64;
    __shared__ float tile[64][65];
    for (int i = threadIdx.x; i < 4096; i += 256) {
        int kk = i >> 6, nn = i & 63;
        tile[kk][nn] = W[(size_t)(k0 + kk) * V_ + n0 + nn];
    }
    __syncthreads();
    for (int i = threadIdx.x; i < 4096; i += 256) {
        int nn = i >> 6, kk = i & 63;
        float v = tile[kk][nn];
        __nv_bfloat16 b0 = __float2bfloat16(v);
        float r1 = v - __bfloat162float(b0);
        __nv_bfloat16 b1 = __float2bfloat16(r1);
        float r2 = r1 - __bfloat162float(b1);
        __nv_bfloat16 b2 = __float2bfloat16(r2);
        size_t o = (size_t)(n0 + nn) * D_ + k0 + kk;
        g_Wsp[o] = b0;
        g_Wsp[WSZ + o] = b1;
        g_Wsp[2 * (size_t)WSZ + o] = b2;
    }
}

// ------------------------------ x prep + split -------------------------------
__global__ void k_prep(const float* __restrict__ Etgt, int t) {
    int r = blockIdx.x;
    int b = r >> 2;
    int tok = g_alive_seq[r * MAXLEN_ + t];
    const float* e = Etgt + (size_t)tok * D_;
    const float* p = g_pooled + b * D_;
    for (int k = threadIdx.x; k < D_; k += blockDim.x) {
        float v = e[k] + p[k];
        __nv_bfloat16 b0 = __float2bfloat16(v);
        float r1 = v - __bfloat162float(b0);
        __nv_bfloat16 b1 = __float2bfloat16(r1);
        float r2 = r1 - __bfloat162float(b1);
        __nv_bfloat16 b2 = __float2bfloat16(r2);
        int o = r * D_ + k;
        g_xsp[o] = b0;
        g_xsp[XSZ + o] = b1;
        g_xsp[2 * XSZ + o] = b2;
    }
}

// ------------------------------ tensor-core GEMM (mma.sync) ------------------
// logits[64][32000] = x @ W + bias via bf16x3: virtual K = 6 products x 512,
// 48 chunks of K=64.  Block = 64M x 128N, 8 warps (2M x 4N grid, warp tile
// 32x32).  2-stage cp.async pipeline, 48 KB static smem, 2 CTAs/SM -> grid
// 250 in one wave.
#define NCHUNK  48
#define STAGE_B 24576                 // 8KB A + 16KB B per stage

__global__ void __launch_bounds__(256, 2) k_gemm(const float* __restrict__ bias) {
    __shared__ __align__(128) char smem[2 * STAGE_B];
    const uint32_t base = smem_u32(smem);
    const int tid  = threadIdx.x;
    const int lane = tid & 31;
    const int wid  = tid >> 5;
    const int warp_m = wid >> 2;      // 0..1  -> m base = warp_m*32
    const int warp_n = wid & 3;       // 0..3  -> n base = warp_n*32
    const int nb = blockIdx.x * 128;

    static const int AI[6] = {0, 0, 1, 0, 1, 2};
    static const int BI[6] = {0, 1, 0, 2, 1, 0};

    float acc[2][4][4];
#pragma unroll
    for (int i = 0; i < 2; i++)
#pragma unroll
        for (int j = 0; j < 4; j++)
#pragma unroll
            for (int q = 0; q < 4; q++) acc[i][j][q] = 0.0f;

    // per-lane ldmatrix geometry
    const int arow  = lane & 15;
    const int acolb = 16 * (lane >> 4);
    const int brow  = (lane & 7) + 8 * ((lane >> 4) & 1);
    const int bcolb = 16 * ((lane >> 3) & 1);

    // gmem->smem copy geometry (per thread: 2 A segs + 4 B segs of 16B)
    const int rA = tid >> 3;          // A row for seg0 (tid+256 -> +32 rows)
    const int fA = tid & 7;

    // issue loads for chunk c into stage st
    auto issue = [&](int c, int st) {
        int p = c >> 3, k0 = (c & 7) * 64;
        const __nv_bfloat16* asrc = g_xsp + AI[p] * XSZ + k0;
        const __nv_bfloat16* bsrc = g_Wsp + (size_t)BI[p] * WSZ + (size_t)nb * D_ + k0;
        uint32_t abase = base + st * STAGE_B;
        uint32_t bbase = abase + 8192;
#pragma unroll
        for (int i = 0; i < 2; i++) {
            int r = rA + i * 32, f = fA;
            cp16(abase + (uint32_t)(r * 128 + ((f * 16) ^ ((r & 7) * 16))),
                 asrc + r * D_ + f * 8);
        }
#pragma unroll
        for (int i = 0; i < 4; i++) {
            int n = rA + i * 32, f = fA;
            cp16(bbase + (uint32_t)(n * 128 + ((f * 16) ^ ((n & 7) * 16))),
                 bsrc + (size_t)n * D_ + f * 8);
        }
    };

    issue(0, 0); CP_COMMIT();
    issue(1, 1); CP_COMMIT();

    for (int c = 0; c < NCHUNK; c++) {
        const int st = c & 1;
        CP_WAIT1();
        __syncthreads();

        const uint32_t As = base + st * STAGE_B;
        const uint32_t Bs = As + 8192;
#pragma unroll
        for (int ks = 0; ks < 4; ks++) {
            uint32_t af[2][4], bf[2][4];
#pragma unroll
            for (int i = 0; i < 2; i++) {
                int r = warp_m * 32 + i * 16 + arow;
                uint32_t addr = As + (uint32_t)(r * 128 + ((ks * 32 + acolb) ^ ((r & 7) * 16)));
                LDMX4(af[i][0], af[i][1], af[i][2], af[i][3], addr);
            }
#pragma unroll
            for (int jp = 0; jp < 2; jp++) {
                int r = warp_n * 32 + jp * 16 + brow;
                uint32_t addr = Bs + (uint32_t)(r * 128 + ((ks * 32 + bcolb) ^ ((r & 7) * 16)));
                LDMX4(bf[jp][0], bf[jp][1], bf[jp][2], bf[jp][3], addr);
            }
#pragma unroll
            for (int i = 0; i < 2; i++) {
#pragma unroll
                for (int jn = 0; jn < 4; jn++) {
                    MMA16816(acc[i][jn], af[i], bf[jn >> 1][(jn & 1) * 2],
                             bf[jn >> 1][(jn & 1) * 2 + 1]);
                }
            }
        }
        __syncthreads();
        if (c + 2 < NCHUNK) issue(c + 2, st);
        CP_COMMIT();   // always commit (possibly empty) so WAIT1 stays aligned
    }

    // epilogue: acc -> g_logits + bias
#pragma unroll
    for (int i = 0; i < 2; i++) {
        int row0 = warp_m * 32 + i * 16 + (lane >> 2);
#pragma unroll
        for (int jn = 0; jn < 4; jn++) {
            int col = nb + warp_n * 32 + jn * 8 + (lane & 3) * 2;
            float2 bz = *reinterpret_cast<const float2*>(bias + col);
            float2 o0 = make_float2(acc[i][jn][0] + bz.x, acc[i][jn][1] + bz.y);
            float2 o1 = make_float2(acc[i][jn][2] + bz.x, acc[i][jn][3] + bz.y);
            *reinterpret_cast<float2*>(g_logits + (size_t)row0 * V_ + col) = o0;
            *reinterpret_cast<float2*>(g_logits + (size_t)(row0 + 8) * V_ + col) = o1;
        }
    }
}

// ------------------------------ fused logsumexp + per-row top-8 --------------
__global__ void __launch_bounds__(256) k_score(int t) {
    int r = blockIdx.x, tid = threadIdx.x;
    const float* lrow = g_logits + (size_t)r * V_;

    // pass 1: online logsumexp with FMA-pipe exp
    float m = -INFINITY, s = 0.0f;
    for (int v = tid; v < V_; v += 256) {
        float x = lrow[v];
        if (x > m) { s = s * pexp(m - x) + 1.0f; m = x; }
        else       { s += pexp(x - m); }
    }
    __shared__ float sm[256], ss[256];
    sm[tid] = m; ss[tid] = s;
    __syncthreads();
    for (int off = 128; off > 0; off >>= 1) {
        if (tid < off) {
            float m1 = sm[tid], s1 = ss[tid];
            float m2 = sm[tid + off], s2 = ss[tid + off];
            if (m2 > m1) { sm[tid] = m2; ss[tid] = s1 * pexp(m1 - m2) + s2; }
            else         { ss[tid] = s1 + s2 * pexp(m2 - m1); }
        }
        __syncthreads();
    }
    __shared__ float rmz[2];
    if (tid == 0) { rmz[0] = sm[0]; rmz[1] = logf(ss[0]); }
    __syncthreads();
    float rm = rmz[0], rz = rmz[1];

    // pass 2: per-thread top-8 under key (ford(score)<<32 | ~flatidx)
    float al = g_alive_lp[r];
    float lpen = (float)(t + 1);
    unsigned int beamBase = (unsigned int)((r & 3) * V_);
    unsigned long long loc[8];
#pragma unroll
    for (int i = 0; i < 8; i++) loc[i] = 0ull;
    for (int v = tid; v < V_; v += 256) {
        float lp = (lrow[v] - rm) - rz;
        float sc = __fdiv_rn(al + lp, lpen);
        unsigned long long key = ((unsigned long long)ford(sc) << 32)
                               | (unsigned long long)(0xFFFFFFFFu - (beamBase + v));
        if (key > loc[7]) {
            loc[7] = key;
#pragma unroll
            for (int i = 7; i > 0; i--) {
                if (loc[i] > loc[i - 1]) {
                    unsigned long long tmp = loc[i]; loc[i] = loc[i - 1]; loc[i - 1] = tmp;
                }
            }
        }
    }

    __shared__ unsigned long long pool[256 * 8];
    __shared__ unsigned long long red[256];
#pragma unroll
    for (int i = 0; i < 8; i++) pool[tid * 8 + i] = loc[i];
    __syncthreads();
    for (int sel = 0; sel < 8; sel++) {
        unsigned long long mx = 0ull;
#pragma unroll
        for (int i = 0; i < 8; i++) mx = umax64(mx, pool[tid * 8 + i]);
        red[tid] = mx;
        __syncthreads();
        for (int off = 128; off > 0; off >>= 1) {
            if (tid < off) red[tid] = umax64(red[tid], red[tid + off]);
            __syncthreads();
        }
        unsigned long long w = red[0];
#pragma unroll
        for (int i = 0; i < 8; i++)
            if (pool[tid * 8 + i] == w) pool[tid * 8 + i] = 0ull;
        if (tid == 0) g_cand[r * 8 + sel] = w;
        __syncthreads();
    }
}

// ------------------------------ beam bookkeeping -----------------------------
__global__ void k_book(int t) {
    int b = threadIdx.x;
    if (b >= B_) return;
    float lpen = (float)(t + 1);

    unsigned long long cand[32];
    for (int j = 0; j < 32; j++) cand[j] = g_cand[(b * BEAM_) * 8 + j];

    float sc[8]; int id[8];
    {
        bool used[32] = {};
        for (int sel = 0; sel < 8; sel++) {
            int best = -1;
            unsigned long long bk = 0ull;
            for (int j = 0; j < 32; j++)
                if (!used[j]) {
                    if (cand[j] > bk || best < 0) { bk = cand[j]; best = j; }
                }
            used[best] = true;
            sc[sel] = finv((unsigned int)(bk >> 32));
            id[sel] = (int)(0xFFFFFFFFu - (unsigned int)bk);
        }
    }

    int tok[8], bix[8], fin[8]; float tlp[8];
    for (int j = 0; j < 8; j++) {
        tok[j] = id[j] % V_;
        bix[j] = (t == 0) ? (j & 3) : (id[j] / V_);
        fin[j] = (tok[j] == 2);
        tlp[j] = sc[j] * lpen;
    }

    int tseq[8][MAXLEN_];
    for (int j = 0; j < 8; j++) {
        const int* sp = g_alive_seq + (b * BEAM_ + bix[j]) * MAXLEN_;
        for (int l = 0; l < MAXLEN_; l++) tseq[j][l] = sp[l];
        tseq[j][t + 1] = tok[j];
    }

    float curr[8];
    for (int j = 0; j < 8; j++) curr[j] = sc[j] + (fin[j] ? -NEG_INF_PEN : 0.0f);
    int aidx[4];
    {
        bool used[8] = {};
        for (int sel = 0; sel < 4; sel++) {
            int best = -1;
            for (int j = 0; j < 8; j++)
                if (!used[j] && (best < 0 || curr[j] > curr[best])) best = j;
            used[best] = true; aidx[sel] = best;
        }
    }
    float nalp[4]; int naseq[4][MAXLEN_];
    for (int k = 0; k < 4; k++) {
        nalp[k] = tlp[aidx[k]];
        for (int l = 0; l < MAXLEN_; l++) naseq[k][l] = tseq[aidx[k]][l];
    }

    float bfp = g_batch_fin[b] ? -NEG_INF_PEN : 0.0f;
    float cs[12]; int cfl[12];
    for (int k = 0; k < 4; k++) {
        cs[k]  = g_fin_scores[b * BEAM_ + k];
        cfl[k] = g_fin_flags[b * BEAM_ + k];
    }
    for (int j = 0; j < 8; j++) {
        cs[4 + j]  = (sc[j] + (fin[j] ? 0.0f : -NEG_INF_PEN)) + bfp;
        cfl[4 + j] = fin[j];
    }
    int fidx[4];
    {
        bool used[12] = {};
        for (int sel = 0; sel < 4; sel++) {
            int best = -1;
            for (int j = 0; j < 12; j++)
                if (!used[j] && (best < 0 || cs[j] > cs[best])) best = j;
            used[best] = true; fidx[sel] = best;
        }
    }
    float nfsc[4]; int nffl[4]; int nfseq[4][MAXLEN_];
    for (int k = 0; k < 4; k++) {
        int j = fidx[k];
        nfsc[k] = cs[j]; nffl[k] = cfl[j];
        if (j < 4) {
            const int* sp = g_fin_seq + (b * BEAM_ + j) * MAXLEN_;
            for (int l = 0; l < MAXLEN_; l++) nfseq[k][l] = sp[l];
        } else {
            for (int l = 0; l < MAXLEN_; l++) nfseq[k][l] = tseq[j - 4][l];
        }
    }

    for (int k = 0; k < 4; k++) {
        g_alive_lp[b * BEAM_ + k]   = nalp[k];
        g_fin_scores[b * BEAM_ + k] = nfsc[k];
        g_fin_flags[b * BEAM_ + k]  = nffl[k];
        for (int l = 0; l < MAXLEN_; l++) {
            g_alive_seq[(b * BEAM_ + k) * MAXLEN_ + l] = naseq[k][l];
            g_fin_seq[(b * BEAM_ + k) * MAXLEN_ + l]   = nfseq[k][l];
        }
    }

    float lb = __fdiv_rn(nalp[0], lpen);
    float lf = nfsc[0] * (nffl[0] ? 1.0f : 0.0f);
    for (int k = 1; k < 4; k++) lf = fminf(lf, nfsc[k] * (nffl[k] ? 1.0f : 0.0f));
    bool allf = nffl[0] && nffl[1] && nffl[2] && nffl[3];
    lf = lf + (allf ? 0.0f : -NEG_INF_PEN);
    if (lf >= lb) g_batch_fin[b] = 1;
}

// ------------------------------ output ---------------------------------------
__global__ void k_out(int* __restrict__ out) {
    int i = threadIdx.x;
    if (i < B_ * MAXLEN_) {
        int b = i / MAXLEN_, l = i % MAXLEN_;
        out[i] = g_fin_seq[(b * BEAM_ + 0) * MAXLEN_ + l];
    }
}

// ------------------------------ launcher -------------------------------------
extern "C" void kernel_launch(void* const* d_in, const int* in_sizes, int n_in,
                              void* d_out, int out_size) {
    (void)in_sizes; (void)n_in; (void)out_size;
    const int*   src  = (const int*)d_in[0];
    const float* Esrc = (const float*)d_in[1];
    const float* Etgt = (const float*)d_in[2];
    const float* W    = (const float*)d_in[3];
    const float* bias = (const float*)d_in[4];

    k_init<<<1, 1024>>>();
    k_pooled<<<B_, 256>>>(src, Esrc);
    k_wprep<<<4000, 256>>>(W);

    for (int t = 0; t < MAXLEN_ - 1; t++) {
        k_prep<<<NR_, 128>>>(Etgt, t);
        k_gemm<<<V_ / 128, 256>>>(bias);
        k_score<<<NR_, 256>>>(t);
        k_book<<<1, B_>>>(t);
    }
    k_out<<<1, 256>>>((int*)d_out);
}